// round 14
// baseline (speedup 1.0000x reference)
#include <cuda_runtime.h>
#include <cuda_bf16.h>
#include <cstdint>

#define SEQ 2048
#define DIM 2048
#define NH 32
#define NKV 8
#define HD 64

// ---------------- scratch (static device globals; no runtime alloc) ----------
__device__ float g_q[SEQ * NH * HD];       // rope+norm output (tf32 bits, scaled)
__device__ float g_k[SEQ * NKV * HD];      // rope+norm output (tf32 bits)
__device__ float g_vT[NKV * HD * SEQ];     // V transposed [n][s], tf32 bits
__device__ float g_gate[SEQ * DIM];        // pre-sigmoid gate (f32)
__device__ float g_att[SEQ * DIM];         // gated attn output (tf32 bits)

// ---------------- helpers ----------------------------------------------------
__device__ __forceinline__ uint32_t f2tf32(float f) {
    uint32_t r;
    asm("cvt.rna.tf32.f32 %0, %1;" : "=r"(r) : "f"(f));
    return r;
}
__device__ __forceinline__ float rtf(float f) { return __uint_as_float(f2tf32(f)); }

__device__ __forceinline__ float ex2(float x) {
    float y;
    asm("ex2.approx.ftz.f32 %0, %1;" : "=f"(y) : "f"(x));
    return y;
}

__device__ __forceinline__ void mma_tf32(float c[4],
                                         uint32_t a0, uint32_t a1, uint32_t a2, uint32_t a3,
                                         uint32_t b0, uint32_t b1)
{
    asm volatile(
        "mma.sync.aligned.m16n8k8.row.col.f32.tf32.tf32.f32 "
        "{%0,%1,%2,%3}, {%4,%5,%6,%7}, {%8,%9}, {%0,%1,%2,%3};"
        : "+f"(c[0]), "+f"(c[1]), "+f"(c[2]), "+f"(c[3])
        : "r"(a0), "r"(a1), "r"(a2), "r"(a3), "r"(b0), "r"(b1));
}

#define LDSM4(r0, r1, r2, r3, addr) \
    asm volatile("ldmatrix.sync.aligned.m8n8.x4.shared.b16 {%0,%1,%2,%3}, [%4];" \
        : "=r"(r0), "=r"(r1), "=r"(r2), "=r"(r3) : "r"(addr))

#define CP16(dst, src) \
    asm volatile("cp.async.cg.shared.global [%0], [%1], 16;" :: "r"(dst), "l"(src))
#define CP_COMMIT() asm volatile("cp.async.commit_group;")
#define CP_WAIT(n)  asm volatile("cp.async.wait_group %0;" :: "n"(n))

__device__ __forceinline__ uint32_t smem_u32(const void* p) {
    return (uint32_t)__cvta_generic_to_shared(p);
}

// ---------------- big GEMM: 4 warps 64x64, reg-staged cvt -------------------
__global__ void __launch_bounds__(128, 2) gemm_big(const float* __restrict__ A,
                                                   const float* __restrict__ B,
                                                   float* __restrict__ C,
                                                   int M, int N, int K)
{
    __shared__ uint32_t As[2][128][20];
    __shared__ uint32_t Bs[2][128][20];
    const uint32_t STAGE = 128 * 20 * 4;

    const int tid  = threadIdx.x;
    const int lane = tid & 31;
    const int warp = tid >> 5;
    const int wm   = warp & 1;
    const int wn   = warp >> 1;
    const int g    = lane >> 2;
    const int tg   = lane & 3;

    const int ar = tid >> 2;
    const int ac = (tid & 3) * 4;

    const float* Ag = A + (blockIdx.y * 128 + ar) * (long)K + ac;
    const float* Bg = B + (blockIdx.x * 128 + ar) * (long)K + ac;

    const uint32_t a_base = smem_u32(&As[0][wm * 64 + (lane & 15)][(lane & 16) ? 4 : 0]);
    const uint32_t b_base = smem_u32(&Bs[0][wn * 64 + (lane & 7) + ((lane & 16) >> 1)][(lane & 8) ? 4 : 0]);

    float c[4][8][4];
    #pragma unroll
    for (int mt = 0; mt < 4; mt++)
        #pragma unroll
        for (int nt = 0; nt < 8; nt++)
            #pragma unroll
            for (int r = 0; r < 4; r++) c[mt][nt][r] = 0.f;

    float4 la[4], lb[4];
    #pragma unroll
    for (int u = 0; u < 4; u++) {
        la[u] = *(const float4*)(Ag + (long)u * 32 * K);
        lb[u] = *(const float4*)(Bg + (long)u * 32 * K);
    }
    #pragma unroll
    for (int u = 0; u < 4; u++) {
        *(uint4*)&As[0][u * 32 + ar][ac] =
            make_uint4(f2tf32(la[u].x), f2tf32(la[u].y), f2tf32(la[u].z), f2tf32(la[u].w));
        *(uint4*)&Bs[0][u * 32 + ar][ac] =
            make_uint4(f2tf32(lb[u].x), f2tf32(lb[u].y), f2tf32(lb[u].z), f2tf32(lb[u].w));
    }

    const int T = K >> 4;
    for (int t = 0; t < T; t++) {
        const int st = t & 1;
        if (t + 1 < T) {
            #pragma unroll
            for (int u = 0; u < 4; u++) {
                la[u] = *(const float4*)(Ag + (t + 1) * 16 + (long)u * 32 * K);
                lb[u] = *(const float4*)(Bg + (t + 1) * 16 + (long)u * 32 * K);
            }
        }
        __syncthreads();

        const uint32_t aa = a_base + st * STAGE;
        const uint32_t bb = b_base + st * STAGE;
        #pragma unroll
        for (int ks = 0; ks < 16; ks += 8) {
            uint32_t af[4][4], bf[8][2];
            #pragma unroll
            for (int mt = 0; mt < 4; mt++)
                LDSM4(af[mt][0], af[mt][1], af[mt][2], af[mt][3],
                      aa + (mt * 16 * 20 + ks) * 4);
            #pragma unroll
            for (int np = 0; np < 4; np++)
                LDSM4(bf[2*np][0], bf[2*np][1], bf[2*np+1][0], bf[2*np+1][1],
                      bb + (np * 16 * 20 + ks) * 4);
            #pragma unroll
            for (int mt = 0; mt < 4; mt++)
                #pragma unroll
                for (int nt = 0; nt < 8; nt++)
                    mma_tf32(c[mt][nt], af[mt][0], af[mt][1], af[mt][2], af[mt][3],
                             bf[nt][0], bf[nt][1]);
        }

        if (t + 1 < T) {
            const int so = st ^ 1;
            #pragma unroll
            for (int u = 0; u < 4; u++) {
                *(uint4*)&As[so][u * 32 + ar][ac] =
                    make_uint4(f2tf32(la[u].x), f2tf32(la[u].y), f2tf32(la[u].z), f2tf32(la[u].w));
                *(uint4*)&Bs[so][u * 32 + ar][ac] =
                    make_uint4(f2tf32(lb[u].x), f2tf32(lb[u].y), f2tf32(lb[u].z), f2tf32(lb[u].w));
            }
        }
    }

    #pragma unroll
    for (int mt = 0; mt < 4; mt++) {
        int row = blockIdx.y * 128 + wm * 64 + mt * 16 + g;
        #pragma unroll
        for (int nt = 0; nt < 8; nt++) {
            int col = blockIdx.x * 128 + wn * 64 + nt * 8 + 2 * tg;
            *(float2*)(C + (long)row * N + col)       = make_float2(c[mt][nt][0], c[mt][nt][1]);
            *(float2*)(C + (long)(row + 8) * N + col) = make_float2(c[mt][nt][2], c[mt][nt][3]);
        }
    }
}

// ---------------- small GEMM (8 warps) + optional transposed tf32 out -------
template <int TRANSB>
__global__ void __launch_bounds__(256, 2) gemm_small(const float* __restrict__ A,
                                                     const float* __restrict__ B,
                                                     float* __restrict__ C,
                                                     int M, int N, int K)
{
    __shared__ uint32_t As[2][128][20];
    __shared__ uint32_t Bs[2][128][20];
    const uint32_t STAGE = 128 * 20 * 4;

    const int tid  = threadIdx.x;
    const int lane = tid & 31;
    const int warp = tid >> 5;
    const int wm   = warp & 1;
    const int wn   = warp >> 1;
    const int g    = lane >> 2;
    const int tg   = lane & 3;

    const int lrow = tid >> 1;
    const int lcol = (tid & 1) * 8;

    const float* Ag = A + (blockIdx.y * 128 + lrow) * (long)K + lcol;
    const float* Bg = B + (blockIdx.x * 128 + lrow) * (long)K + lcol;

    const uint32_t a_base = smem_u32(&As[0][wm * 64 + (lane & 15)][(lane & 16) ? 4 : 0]);
    const uint32_t b_base = smem_u32(&Bs[0][wn * 32 + (lane & 7) + ((lane & 16) >> 1)][(lane & 8) ? 4 : 0]);

    float c[4][4][4];
    #pragma unroll
    for (int mt = 0; mt < 4; mt++)
        #pragma unroll
        for (int nt = 0; nt < 4; nt++)
            #pragma unroll
            for (int r = 0; r < 4; r++) c[mt][nt][r] = 0.f;

    float4 pa0 = *(const float4*)(Ag + 0);
    float4 pa1 = *(const float4*)(Ag + 4);
    float4 pb0 = *(const float4*)(Bg + 0);
    float4 pb1 = *(const float4*)(Bg + 4);
    *(uint4*)&As[0][lrow][lcol]     = make_uint4(f2tf32(pa0.x), f2tf32(pa0.y), f2tf32(pa0.z), f2tf32(pa0.w));
    *(uint4*)&As[0][lrow][lcol + 4] = make_uint4(f2tf32(pa1.x), f2tf32(pa1.y), f2tf32(pa1.z), f2tf32(pa1.w));
    *(uint4*)&Bs[0][lrow][lcol]     = make_uint4(f2tf32(pb0.x), f2tf32(pb0.y), f2tf32(pb0.z), f2tf32(pb0.w));
    *(uint4*)&Bs[0][lrow][lcol + 4] = make_uint4(f2tf32(pb1.x), f2tf32(pb1.y), f2tf32(pb1.z), f2tf32(pb1.w));

    const int T = K >> 4;
    for (int t = 0; t < T; t++) {
        const int st = t & 1;
        if (t + 1 < T) {
            pa0 = *(const float4*)(Ag + (t+1)*16);     pa1 = *(const float4*)(Ag + (t+1)*16 + 4);
            pb0 = *(const float4*)(Bg + (t+1)*16);     pb1 = *(const float4*)(Bg + (t+1)*16 + 4);
        }
        __syncthreads();

        const uint32_t aa = a_base + st * STAGE;
        const uint32_t bb = b_base + st * STAGE;
        #pragma unroll
        for (int ks = 0; ks < 16; ks += 8) {
            uint32_t af[4][4], bf[4][2];
            #pragma unroll
            for (int mt = 0; mt < 4; mt++)
                LDSM4(af[mt][0], af[mt][1], af[mt][2], af[mt][3],
                      aa + (mt * 16 * 20 + ks) * 4);
            #pragma unroll
            for (int np = 0; np < 2; np++)
                LDSM4(bf[2*np][0], bf[2*np][1], bf[2*np+1][0], bf[2*np+1][1],
                      bb + (np * 16 * 20 + ks) * 4);
            #pragma unroll
            for (int mt = 0; mt < 4; mt++)
                #pragma unroll
                for (int nt = 0; nt < 4; nt++)
                    mma_tf32(c[mt][nt], af[mt][0], af[mt][1], af[mt][2], af[mt][3],
                             bf[nt][0], bf[nt][1]);
        }

        if (t + 1 < T) {
            const int so = st ^ 1;
            *(uint4*)&As[so][lrow][lcol]     = make_uint4(f2tf32(pa0.x), f2tf32(pa0.y), f2tf32(pa0.z), f2tf32(pa0.w));
            *(uint4*)&As[so][lrow][lcol + 4] = make_uint4(f2tf32(pa1.x), f2tf32(pa1.y), f2tf32(pa1.z), f2tf32(pa1.w));
            *(uint4*)&Bs[so][lrow][lcol]     = make_uint4(f2tf32(pb0.x), f2tf32(pb0.y), f2tf32(pb0.z), f2tf32(pb0.w));
            *(uint4*)&Bs[so][lrow][lcol + 4] = make_uint4(f2tf32(pb1.x), f2tf32(pb1.y), f2tf32(pb1.z), f2tf32(pb1.w));
        }
    }

    #pragma unroll
    for (int mt = 0; mt < 4; mt++) {
        int row = blockIdx.y * 128 + wm * 64 + mt * 16 + g;
        #pragma unroll
        for (int nt = 0; nt < 4; nt++) {
            int col = blockIdx.x * 128 + wn * 32 + nt * 8 + 2 * tg;
            if (TRANSB) {
                C[(long)col * M + row]           = rtf(c[mt][nt][0]);
                C[(long)(col + 1) * M + row]     = rtf(c[mt][nt][1]);
                C[(long)col * M + row + 8]       = rtf(c[mt][nt][2]);
                C[(long)(col + 1) * M + row + 8] = rtf(c[mt][nt][3]);
            } else {
                *(float2*)(C + (long)row * N + col)       = make_float2(c[mt][nt][0], c[mt][nt][1]);
                *(float2*)(C + (long)(row + 8) * N + col) = make_float2(c[mt][nt][2], c[mt][nt][3]);
            }
        }
    }
}

// ---------------- fused RoPE + RMSNorm + tf32 round (+scale) ----------------
__global__ void rope_rmsnorm(float* __restrict__ t, const float* __restrict__ cosb,
                             const float* __restrict__ sinb, const float* __restrict__ w,
                             int nheads, int nrows, float scale)
{
    int row  = blockIdx.x * 8 + (threadIdx.x >> 5);
    if (row >= nrows) return;
    int lane = threadIdx.x & 31;
    int s    = row / nheads;

    float* p = t + row * HD;
    float2 xv = ((float2*)p)[lane];
    float c  = cosb[s * (HD / 2) + lane];
    float sn = sinb[s * (HD / 2) + lane];
    float orr = xv.x * c - xv.y * sn;
    float oi  = xv.x * sn + xv.y * c;

    float ss = orr * orr + oi * oi;
    #pragma unroll
    for (int o = 16; o; o >>= 1) ss += __shfl_xor_sync(0xffffffffu, ss, o);
    float inv = rsqrtf(ss * (1.f / HD) + 1e-6f) * scale;

    float2 wv = ((const float2*)w)[lane];
    ((float2*)p)[lane] = make_float2(rtf(orr * inv * wv.x), rtf(oi * inv * wv.y));
}

// ---------------- tensor-core flash attention: 128-row Q tile, 4 warps ------
#define KS_STAGE 4352
#define VS_OFF   8704
#define VS_STAGE 4352
#define ATTN_SMEM ((VS_OFF + 2 * VS_STAGE) * 4)

__global__ void __launch_bounds__(128) attn_tc(const float* __restrict__ q,
                                               const float* __restrict__ k,
                                               const float* __restrict__ vT,
                                               const float* __restrict__ gate,
                                               float* __restrict__ o)
{
    extern __shared__ uint32_t dsm[];
    const uint32_t sbase = smem_u32(dsm);

    const int b    = 15 - blockIdx.x;
    const int h    = blockIdx.y;
    const int kvh  = h >> 2;
    const int tid  = threadIdx.x;
    const int lane = tid & 31;
    const int w    = tid >> 5;
    const int g    = lane >> 2;
    const int tg   = lane & 3;
    const int qi0  = b * 128;
    const int KT   = 2 * b + 2;

    const int lr = tid >> 1;
    const int lc = (tid & 1) * 32;

    auto issueK = [&](int kb, int st) {
        const float* kp = k + (((long)(kb * 64 + lr)) * NKV + kvh) * HD + lc;
        uint32_t kd = sbase + (st * KS_STAGE + lr * 68 + lc) * 4;
        #pragma unroll
        for (int u = 0; u < 8; u++) CP16(kd + u * 16, kp + u * 4);
    };
    auto issueV = [&](int kb, int st) {
        const float* vp = vT + ((long)(kvh * HD + lr)) * SEQ + kb * 64 + lc;
        uint32_t vd = sbase + (VS_OFF + st * VS_STAGE + lr * 68 + lc) * 4;
        #pragma unroll
        for (int u = 0; u < 8; u++) CP16(vd + u * 16, vp + u * 4);
    };

    issueK(0, 0); CP_COMMIT();

    {
        const float* qp = q + (((long)(qi0 + tid)) * NH + h) * HD;
        uint32_t* dst = dsm + VS_OFF + tid * 68;
        #pragma unroll
        for (int u = 0; u < 16; u++)
            *(float4*)(dst + u * 4) = *(const float4*)(qp + u * 4);
    }
    __syncthreads();

    uint32_t qf[2][8][4];
    #pragma unroll
    for (int rg = 0; rg < 2; rg++) {
        const uint32_t qaddr = sbase + (VS_OFF + (w * 32 + rg * 16 + (lane & 15)) * 68
                                        + ((lane & 16) ? 4 : 0)) * 4;
        #pragma unroll
        for (int ks = 0; ks < 8; ks++)
            LDSM4(qf[rg][ks][0], qf[rg][ks][1], qf[rg][ks][2], qf[rg][ks][3],
                  qaddr + ks * 32);
    }
    __syncthreads();

    issueV(0, 0); CP_COMMIT();
    issueK(1, 1); issueV(1, 1); CP_COMMIT();

    const uint32_t kpat = sbase + (((lane & 7) + ((lane & 16) >> 1)) * 68 + ((lane & 8) ? 4 : 0)) * 4;
    const uint32_t vpat = sbase + (VS_OFF + ((lane & 7) + ((lane & 16) >> 1)) * 68 + ((lane & 8) ? 4 : 0)) * 4;

    float oacc[2][8][4];
    #pragma unroll
    for (int rg = 0; rg < 2; rg++)
        #pragma unroll
        for (int nt = 0; nt < 8; nt++)
            #pragma unroll
            for (int r = 0; r < 4; r++) oacc[rg][nt][r] = 0.f;
    float m[4] = {-1e30f, -1e30f, -1e30f, -1e30f};
    float l[4] = {0.f, 0.f, 0.f, 0.f};

    const int s0l  = (lane & ~3) + (tg >> 1);
    const int s2l  = s0l + 2;
    const bool odd = tg & 1;

    for (int kb = 0; kb < KT; kb++) {
        const int st = kb & 1;
        if (kb < KT - 1) { CP_WAIT(1); } else { CP_WAIT(0); }
        __syncthreads();

        float sc[2][8][4];
        #pragma unroll
        for (int rg = 0; rg < 2; rg++)
            #pragma unroll
            for (int nt = 0; nt < 8; nt++)
                #pragma unroll
                for (int r = 0; r < 4; r++) sc[rg][nt][r] = 0.f;

        const uint32_t kst = kpat + st * (KS_STAGE * 4);
        #pragma unroll
        for (int ks = 0; ks < 8; ks++) {
            #pragma unroll
            for (int np = 0; np < 4; np++) {
                uint32_t b00, b01, b10, b11;
                LDSM4(b00, b01, b10, b11, kst + (np * 16 * 68 + ks * 8) * 4);
                #pragma unroll
                for (int rg = 0; rg < 2; rg++) {
                    mma_tf32(sc[rg][2*np],   qf[rg][ks][0], qf[rg][ks][1],
                             qf[rg][ks][2], qf[rg][ks][3], b00, b01);
                    mma_tf32(sc[rg][2*np+1], qf[rg][ks][0], qf[rg][ks][1],
                             qf[rg][ks][2], qf[rg][ks][3], b10, b11);
                }
            }
        }

        if (kb >= 2 * b) {
            const int coff = (kb - 2 * b) * 64;
            #pragma unroll
            for (int rg = 0; rg < 2; rg++) {
                int r0 = w * 32 + rg * 16 + g, r1 = r0 + 8;
                #pragma unroll
                for (int nt = 0; nt < 8; nt++) {
                    int c0 = nt * 8 + 2 * tg + coff, c1 = c0 + 1;
                    if (c0 > r0) sc[rg][nt][0] = -1e30f;
                    if (c1 > r0) sc[rg][nt][1] = -1e30f;
                    if (c0 > r1) sc[rg][nt][2] = -1e30f;
                    if (c1 > r1) sc[rg][nt][3] = -1e30f;
                }
            }
        }

        #pragma unroll
        for (int rg = 0; rg < 2; rg++) {
            const int ia = rg * 2, ib = ia + 1;
            float mta = -1e30f, mtb = -1e30f;
            #pragma unroll
            for (int nt = 0; nt < 8; nt++) {
                mta = fmaxf(mta, fmaxf(sc[rg][nt][0], sc[rg][nt][1]));
                mtb = fmaxf(mtb, fmaxf(sc[rg][nt][2], sc[rg][nt][3]));
            }
            mta = fmaxf(mta, __shfl_xor_sync(0xffffffffu, mta, 1));
            mta = fmaxf(mta, __shfl_xor_sync(0xffffffffu, mta, 2));
            mtb = fmaxf(mtb, __shfl_xor_sync(0xffffffffu, mtb, 1));
            mtb = fmaxf(mtb, __shfl_xor_sync(0xffffffffu, mtb, 2));

            float mna = fmaxf(m[ia], mta), mnb = fmaxf(m[ib], mtb);
            float aa = ex2(m[ia] - mna),   ab = ex2(m[ib] - mnb);
            m[ia] = mna; m[ib] = mnb;

            float rsa = 0.f, rsb = 0.f;
            #pragma unroll
            for (int nt = 0; nt < 8; nt++) {
                float e0 = ex2(sc[rg][nt][0] - mna);
                float e1 = ex2(sc[rg][nt][1] - mna);
                float e2 = ex2(sc[rg][nt][2] - mnb);
                float e3 = ex2(sc[rg][nt][3] - mnb);
                rsa += e0 + e1;  rsb += e2 + e3;
                sc[rg][nt][0] = __uint_as_float(f2tf32(e0));
                sc[rg][nt][1] = __uint_as_float(f2tf32(e1));
                sc[rg][nt][2] = __uint_as_float(f2tf32(e2));
                sc[rg][nt][3] = __uint_as_float(f2tf32(e3));
            }
            rsa += __shfl_xor_sync(0xffffffffu, rsa, 1);
            rsa += __shfl_xor_sync(0xffffffffu, rsa, 2);
            rsb += __shfl_xor_sync(0xffffffffu, rsb, 1);
            rsb += __shfl_xor_sync(0xffffffffu, rsb, 2);
            l[ia] = l[ia] * aa + rsa;
            l[ib] = l[ib] * ab + rsb;

            #pragma unroll
            for (int nt = 0; nt < 8; nt++) {
                oacc[rg][nt][0] *= aa; oacc[rg][nt][1] *= aa;
                oacc[rg][nt][2] *= ab; oacc[rg][nt][3] *= ab;
            }
        }

        const uint32_t vst = vpat + st * (VS_STAGE * 4);
        #pragma unroll
        for (int ks = 0; ks < 8; ks++) {
            uint32_t pa[2][4];
            #pragma unroll
            for (int rg = 0; rg < 2; rg++) {
                float u0 = __shfl_sync(0xffffffffu, sc[rg][ks][0], s0l);
                float u1 = __shfl_sync(0xffffffffu, sc[rg][ks][1], s0l);
                float u2 = __shfl_sync(0xffffffffu, sc[rg][ks][2], s0l);
                float u3 = __shfl_sync(0xffffffffu, sc[rg][ks][3], s0l);
                float v0 = __shfl_sync(0xffffffffu, sc[rg][ks][0], s2l);
                float v1 = __shfl_sync(0xffffffffu, sc[rg][ks][1], s2l);
                float v2 = __shfl_sync(0xffffffffu, sc[rg][ks][2], s2l);
                float v3 = __shfl_sync(0xffffffffu, sc[rg][ks][3], s2l);
                pa[rg][0] = __float_as_uint(odd ? u1 : u0);
                pa[rg][1] = __float_as_uint(odd ? u3 : u2);
                pa[rg][2] = __float_as_uint(odd ? v1 : v0);
                pa[rg][3] = __float_as_uint(odd ? v3 : v2);
            }
            #pragma unroll
            for (int np = 0; np < 4; np++) {
                uint32_t b00, b01, b10, b11;
                LDSM4(b00, b01, b10, b11, vst + (np * 16 * 68 + ks * 8) * 4);
                #pragma unroll
                for (int rg = 0; rg < 2; rg++) {
                    mma_tf32(oacc[rg][2*np],   pa[rg][0], pa[rg][1], pa[rg][2], pa[rg][3], b00, b01);
                    mma_tf32(oacc[rg][2*np+1], pa[rg][0], pa[rg][1], pa[rg][2], pa[rg][3], b10, b11);
                }
            }
        }

        __syncthreads();
        if (kb + 2 < KT) { issueK(kb + 2, st); issueV(kb + 2, st); CP_COMMIT(); }
    }

    #pragma unroll
    for (int rg = 0; rg < 2; rg++) {
        float ila = 1.f / l[rg * 2], ilb = 1.f / l[rg * 2 + 1];
        int row0 = qi0 + w * 32 + rg * 16 + g;
        int row1 = row0 + 8;
        #pragma unroll
        for (int nt = 0; nt < 8; nt++) {
            int d = nt * 8 + 2 * tg;
            float2 ga = *(const float2*)(gate + (long)row0 * DIM + h * HD + d);
            float2 gb = *(const float2*)(gate + (long)row1 * DIM + h * HD + d);
            float2 o0, o1;
            o0.x = rtf(oacc[rg][nt][0] * ila * (1.f / (1.f + __expf(-ga.x))));
            o0.y = rtf(oacc[rg][nt][1] * ila * (1.f / (1.f + __expf(-ga.y))));
            o1.x = rtf(oacc[rg][nt][2] * ilb * (1.f / (1.f + __expf(-gb.x))));
            o1.y = rtf(oacc[rg][nt][3] * ilb * (1.f / (1.f + __expf(-gb.y))));
            *(float2*)(o + (long)row0 * DIM + h * HD + d) = o0;
            *(float2*)(o + (long)row1 * DIM + h * HD + d) = o1;
        }
    }
}

// ---------------- launcher: fork-join multi-stream overlap -------------------
extern "C" void kernel_launch(void* const* d_in, const int* in_sizes, int n_in,
                              void* d_out, int out_size)
{
    const float* x    = (const float*)d_in[0];
    const float* cosb = (const float*)d_in[1];
    const float* sinb = (const float*)d_in[2];
    const float* wq   = (const float*)d_in[3];
    const float* wk   = (const float*)d_in[4];
    const float* wv   = (const float*)d_in[5];
    const float* wo   = (const float*)d_in[6];
    const float* wg   = (const float*)d_in[7];
    const float* qn   = (const float*)d_in[8];
    const float* kn   = (const float*)d_in[9];
    float* out = (float*)d_out;

    float *qb, *kb, *vT, *gb, *ab;
    cudaGetSymbolAddress((void**)&qb, g_q);
    cudaGetSymbolAddress((void**)&kb, g_k);
    cudaGetSymbolAddress((void**)&vT, g_vT);
    cudaGetSymbolAddress((void**)&gb, g_gate);
    cudaGetSymbolAddress((void**)&ab, g_att);

    static cudaStream_t sB = nullptr, sC = nullptr;
    static cudaEvent_t  eF = nullptr, eB = nullptr, eC = nullptr;
    if (!sB) {   // one-time resource setup (no device memory involved)
        cudaStreamCreateWithFlags(&sB, cudaStreamNonBlocking);
        cudaStreamCreateWithFlags(&sC, cudaStreamNonBlocking);
        cudaEventCreateWithFlags(&eF, cudaEventDisableTiming);
        cudaEventCreateWithFlags(&eB, cudaEventDisableTiming);
        cudaEventCreateWithFlags(&eC, cudaEventDisableTiming);
        cudaFuncSetAttribute(attn_tc, cudaFuncAttributeMaxDynamicSharedMemorySize, ATTN_SMEM);
    }

    const float QSCALE = 0.125f * 1.44269504088896f;

    // fork: side streams take the small K/V projections (+ k RoPE)
    cudaEventRecord(eF, 0);
    cudaStreamWaitEvent(sB, eF, 0);
    cudaStreamWaitEvent(sC, eF, 0);

    gemm_small<0><<<dim3((NKV * HD) / 128, SEQ / 128), 256, 0, sB>>>(x, wk, kb, SEQ, NKV * HD, DIM);
    rope_rmsnorm<<<(SEQ * NKV) / 8, 256, 0, sB>>>(kb, cosb, sinb, kn, NKV, SEQ * NKV, 1.0f);
    cudaEventRecord(eB, sB);

    gemm_small<1><<<dim3((NKV * HD) / 128, SEQ / 128), 256, 0, sC>>>(x, wv, vT, SEQ, NKV * HD, DIM);
    cudaEventRecord(eC, sC);

    // main stream: the two big projections + q RoPE
    gemm_big<<<dim3(DIM / 128, SEQ / 128), 128>>>(x, wq, qb, SEQ, DIM, DIM);
    rope_rmsnorm<<<(SEQ * NH) / 8, 256>>>(qb, cosb, sinb, qn, NH, SEQ * NH, QSCALE);
    gemm_big<<<dim3(DIM / 128, SEQ / 128), 128>>>(x, wg, gb, SEQ, DIM, DIM);

    // join
    cudaStreamWaitEvent(0, eB, 0);
    cudaStreamWaitEvent(0, eC, 0);

    // attention + fused sigmoid gate
    attn_tc<<<dim3(SEQ / 128, NH), 128, ATTN_SMEM>>>(qb, kb, vT, gb, ab);

    // output projection
    gemm_big<<<dim3(DIM / 128, SEQ / 128), 128>>>(ab, wo, out, SEQ, DIM, DIM);
}

// round 15
// speedup vs baseline: 1.5103x; 1.5103x over previous
#include <cuda_runtime.h>
#include <cuda_bf16.h>
#include <cstdint>

#define SEQ 2048
#define DIM 2048
#define NH 32
#define NKV 8
#define HD 64

// ---------------- scratch (static device globals; no runtime alloc) ----------
__device__ float g_q[SEQ * NH * HD];       // rope+norm output (tf32 bits, scaled)
__device__ float g_k[SEQ * NKV * HD];      // K proj (f32), then rope output (tf32 bits)
__device__ float g_vT[NKV * HD * SEQ];     // V transposed [n][s], tf32 bits
__device__ float g_gate[SEQ * DIM];        // pre-sigmoid gate (f32)
__device__ float g_att[SEQ * DIM];         // gated attn output (tf32 bits)

// ---------------- helpers ----------------------------------------------------
__device__ __forceinline__ uint32_t f2tf32(float f) {
    uint32_t r;
    asm("cvt.rna.tf32.f32 %0, %1;" : "=r"(r) : "f"(f));
    return r;
}
__device__ __forceinline__ float rtf(float f) { return __uint_as_float(f2tf32(f)); }

__device__ __forceinline__ float ex2(float x) {
    float y;
    asm("ex2.approx.ftz.f32 %0, %1;" : "=f"(y) : "f"(x));
    return y;
}

__device__ __forceinline__ void mma_tf32(float c[4],
                                         uint32_t a0, uint32_t a1, uint32_t a2, uint32_t a3,
                                         uint32_t b0, uint32_t b1)
{
    asm volatile(
        "mma.sync.aligned.m16n8k8.row.col.f32.tf32.tf32.f32 "
        "{%0,%1,%2,%3}, {%4,%5,%6,%7}, {%8,%9}, {%0,%1,%2,%3};"
        : "+f"(c[0]), "+f"(c[1]), "+f"(c[2]), "+f"(c[3])
        : "r"(a0), "r"(a1), "r"(a2), "r"(a3), "r"(b0), "r"(b1));
}

#define LDSM4(r0, r1, r2, r3, addr) \
    asm volatile("ldmatrix.sync.aligned.m8n8.x4.shared.b16 {%0,%1,%2,%3}, [%4];" \
        : "=r"(r0), "=r"(r1), "=r"(r2), "=r"(r3) : "r"(addr))

#define CP16(dst, src) \
    asm volatile("cp.async.cg.shared.global [%0], [%1], 16;" :: "r"(dst), "l"(src))
#define CP_COMMIT() asm volatile("cp.async.commit_group;")
#define CP_WAIT(n)  asm volatile("cp.async.wait_group %0;" :: "n"(n))

__device__ __forceinline__ uint32_t smem_u32(const void* p) {
    return (uint32_t)__cvta_generic_to_shared(p);
}

// ---------------- big GEMM: 4 warps 64x64; optional fused q-RoPE+RMSNorm ----
// FUSE_ROPE=1: warp column tile (64 cols) == one head; applies RoPE (thread-
// local even/odd pairs), RMSNorm (quad reduction), qn weight, scale, tf32 round.
template <int FUSE_ROPE>
__global__ void __launch_bounds__(128, 2) gemm_big(const float* __restrict__ A,
                                                   const float* __restrict__ B,
                                                   float* __restrict__ C,
                                                   int M, int N, int K,
                                                   const float* __restrict__ cosb,
                                                   const float* __restrict__ sinb,
                                                   const float* __restrict__ nw,
                                                   float scale)
{
    __shared__ uint32_t As[2][128][20];
    __shared__ uint32_t Bs[2][128][20];
    const uint32_t STAGE = 128 * 20 * 4;

    const int tid  = threadIdx.x;
    const int lane = tid & 31;
    const int warp = tid >> 5;
    const int wm   = warp & 1;
    const int wn   = warp >> 1;
    const int g    = lane >> 2;
    const int tg   = lane & 3;

    const int ar = tid >> 2;
    const int ac = (tid & 3) * 4;

    const float* Ag = A + (blockIdx.y * 128 + ar) * (long)K + ac;
    const float* Bg = B + (blockIdx.x * 128 + ar) * (long)K + ac;

    const uint32_t a_base = smem_u32(&As[0][wm * 64 + (lane & 15)][(lane & 16) ? 4 : 0]);
    const uint32_t b_base = smem_u32(&Bs[0][wn * 64 + (lane & 7) + ((lane & 16) >> 1)][(lane & 8) ? 4 : 0]);

    float c[4][8][4];
    #pragma unroll
    for (int mt = 0; mt < 4; mt++)
        #pragma unroll
        for (int nt = 0; nt < 8; nt++)
            #pragma unroll
            for (int r = 0; r < 4; r++) c[mt][nt][r] = 0.f;

    float4 la[4], lb[4];
    #pragma unroll
    for (int u = 0; u < 4; u++) {
        la[u] = *(const float4*)(Ag + (long)u * 32 * K);
        lb[u] = *(const float4*)(Bg + (long)u * 32 * K);
    }
    #pragma unroll
    for (int u = 0; u < 4; u++) {
        *(uint4*)&As[0][u * 32 + ar][ac] =
            make_uint4(f2tf32(la[u].x), f2tf32(la[u].y), f2tf32(la[u].z), f2tf32(la[u].w));
        *(uint4*)&Bs[0][u * 32 + ar][ac] =
            make_uint4(f2tf32(lb[u].x), f2tf32(lb[u].y), f2tf32(lb[u].z), f2tf32(lb[u].w));
    }

    const int T = K >> 4;
    for (int t = 0; t < T; t++) {
        const int st = t & 1;
        if (t + 1 < T) {
            #pragma unroll
            for (int u = 0; u < 4; u++) {
                la[u] = *(const float4*)(Ag + (t + 1) * 16 + (long)u * 32 * K);
                lb[u] = *(const float4*)(Bg + (t + 1) * 16 + (long)u * 32 * K);
            }
        }
        __syncthreads();

        const uint32_t aa = a_base + st * STAGE;
        const uint32_t bb = b_base + st * STAGE;
        #pragma unroll
        for (int ks = 0; ks < 16; ks += 8) {
            uint32_t af[4][4], bf[8][2];
            #pragma unroll
            for (int mt = 0; mt < 4; mt++)
                LDSM4(af[mt][0], af[mt][1], af[mt][2], af[mt][3],
                      aa + (mt * 16 * 20 + ks) * 4);
            #pragma unroll
            for (int np = 0; np < 4; np++)
                LDSM4(bf[2*np][0], bf[2*np][1], bf[2*np+1][0], bf[2*np+1][1],
                      bb + (np * 16 * 20 + ks) * 4);
            #pragma unroll
            for (int mt = 0; mt < 4; mt++)
                #pragma unroll
                for (int nt = 0; nt < 8; nt++)
                    mma_tf32(c[mt][nt], af[mt][0], af[mt][1], af[mt][2], af[mt][3],
                             bf[nt][0], bf[nt][1]);
        }

        if (t + 1 < T) {
            const int so = st ^ 1;
            #pragma unroll
            for (int u = 0; u < 4; u++) {
                *(uint4*)&As[so][u * 32 + ar][ac] =
                    make_uint4(f2tf32(la[u].x), f2tf32(la[u].y), f2tf32(la[u].z), f2tf32(la[u].w));
                *(uint4*)&Bs[so][u * 32 + ar][ac] =
                    make_uint4(f2tf32(lb[u].x), f2tf32(lb[u].y), f2tf32(lb[u].z), f2tf32(lb[u].w));
            }
        }
    }

    if (FUSE_ROPE) {
        // RoPE: thread-local even/odd pairs; pair index d = nt*4 + tg (0..31)
        #pragma unroll
        for (int mt = 0; mt < 4; mt++) {
            int row0 = blockIdx.y * 128 + wm * 64 + mt * 16 + g;
            int row1 = row0 + 8;
            float ss0 = 0.f, ss1 = 0.f;
            #pragma unroll
            for (int nt = 0; nt < 8; nt++) {
                int d = nt * 4 + tg;
                float c0 = cosb[row0 * (HD/2) + d], s0 = sinb[row0 * (HD/2) + d];
                float c1 = cosb[row1 * (HD/2) + d], s1 = sinb[row1 * (HD/2) + d];
                float xr0 = c[mt][nt][0], xi0 = c[mt][nt][1];
                float xr1 = c[mt][nt][2], xi1 = c[mt][nt][3];
                c[mt][nt][0] = xr0 * c0 - xi0 * s0;
                c[mt][nt][1] = xr0 * s0 + xi0 * c0;
                c[mt][nt][2] = xr1 * c1 - xi1 * s1;
                c[mt][nt][3] = xr1 * s1 + xi1 * c1;
                ss0 += c[mt][nt][0]*c[mt][nt][0] + c[mt][nt][1]*c[mt][nt][1];
                ss1 += c[mt][nt][2]*c[mt][nt][2] + c[mt][nt][3]*c[mt][nt][3];
            }
            ss0 += __shfl_xor_sync(0xffffffffu, ss0, 1);
            ss0 += __shfl_xor_sync(0xffffffffu, ss0, 2);
            ss1 += __shfl_xor_sync(0xffffffffu, ss1, 1);
            ss1 += __shfl_xor_sync(0xffffffffu, ss1, 2);
            float inv0 = rsqrtf(ss0 * (1.f / HD) + 1e-6f) * scale;
            float inv1 = rsqrtf(ss1 * (1.f / HD) + 1e-6f) * scale;
            #pragma unroll
            for (int nt = 0; nt < 8; nt++) {
                int dc = nt * 8 + 2 * tg;
                float w0 = nw[dc], w1 = nw[dc + 1];
                c[mt][nt][0] = rtf(c[mt][nt][0] * inv0 * w0);
                c[mt][nt][1] = rtf(c[mt][nt][1] * inv0 * w1);
                c[mt][nt][2] = rtf(c[mt][nt][2] * inv1 * w0);
                c[mt][nt][3] = rtf(c[mt][nt][3] * inv1 * w1);
            }
        }
    }

    #pragma unroll
    for (int mt = 0; mt < 4; mt++) {
        int row = blockIdx.y * 128 + wm * 64 + mt * 16 + g;
        #pragma unroll
        for (int nt = 0; nt < 8; nt++) {
            int col = blockIdx.x * 128 + wn * 64 + nt * 8 + 2 * tg;
            *(float2*)(C + (long)row * N + col)       = make_float2(c[mt][nt][0], c[mt][nt][1]);
            *(float2*)(C + (long)(row + 8) * N + col) = make_float2(c[mt][nt][2], c[mt][nt][3]);
        }
    }
}

// ---------------- merged K+V projection: grid.z picks weight/output ---------
// z=0: K = x @ wk.T  -> Ck[M][512] (f32, rope'd later)
// z=1: V = x @ wv.T  -> Cv transposed [512][M] (tf32 bits)
__global__ void __launch_bounds__(256, 2) gemm_kv(const float* __restrict__ A,
                                                  const float* __restrict__ Bk,
                                                  const float* __restrict__ Bv,
                                                  float* __restrict__ Ck,
                                                  float* __restrict__ Cv,
                                                  int M, int N, int K)
{
    __shared__ uint32_t As[2][128][20];
    __shared__ uint32_t Bs[2][128][20];
    const uint32_t STAGE = 128 * 20 * 4;

    const int zz   = blockIdx.z;
    const float* B = zz ? Bv : Bk;

    const int tid  = threadIdx.x;
    const int lane = tid & 31;
    const int warp = tid >> 5;
    const int wm   = warp & 1;
    const int wn   = warp >> 1;
    const int g    = lane >> 2;
    const int tg   = lane & 3;

    const int lrow = tid >> 1;
    const int lcol = (tid & 1) * 8;

    const float* Ag = A + (blockIdx.y * 128 + lrow) * (long)K + lcol;
    const float* Bg = B + (blockIdx.x * 128 + lrow) * (long)K + lcol;

    const uint32_t a_base = smem_u32(&As[0][wm * 64 + (lane & 15)][(lane & 16) ? 4 : 0]);
    const uint32_t b_base = smem_u32(&Bs[0][wn * 32 + (lane & 7) + ((lane & 16) >> 1)][(lane & 8) ? 4 : 0]);

    float c[4][4][4];
    #pragma unroll
    for (int mt = 0; mt < 4; mt++)
        #pragma unroll
        for (int nt = 0; nt < 4; nt++)
            #pragma unroll
            for (int r = 0; r < 4; r++) c[mt][nt][r] = 0.f;

    float4 pa0 = *(const float4*)(Ag + 0);
    float4 pa1 = *(const float4*)(Ag + 4);
    float4 pb0 = *(const float4*)(Bg + 0);
    float4 pb1 = *(const float4*)(Bg + 4);
    *(uint4*)&As[0][lrow][lcol]     = make_uint4(f2tf32(pa0.x), f2tf32(pa0.y), f2tf32(pa0.z), f2tf32(pa0.w));
    *(uint4*)&As[0][lrow][lcol + 4] = make_uint4(f2tf32(pa1.x), f2tf32(pa1.y), f2tf32(pa1.z), f2tf32(pa1.w));
    *(uint4*)&Bs[0][lrow][lcol]     = make_uint4(f2tf32(pb0.x), f2tf32(pb0.y), f2tf32(pb0.z), f2tf32(pb0.w));
    *(uint4*)&Bs[0][lrow][lcol + 4] = make_uint4(f2tf32(pb1.x), f2tf32(pb1.y), f2tf32(pb1.z), f2tf32(pb1.w));

    const int T = K >> 4;
    for (int t = 0; t < T; t++) {
        const int st = t & 1;
        if (t + 1 < T) {
            pa0 = *(const float4*)(Ag + (t+1)*16);     pa1 = *(const float4*)(Ag + (t+1)*16 + 4);
            pb0 = *(const float4*)(Bg + (t+1)*16);     pb1 = *(const float4*)(Bg + (t+1)*16 + 4);
        }
        __syncthreads();

        const uint32_t aa = a_base + st * STAGE;
        const uint32_t bb = b_base + st * STAGE;
        #pragma unroll
        for (int ks = 0; ks < 16; ks += 8) {
            uint32_t af[4][4], bf[4][2];
            #pragma unroll
            for (int mt = 0; mt < 4; mt++)
                LDSM4(af[mt][0], af[mt][1], af[mt][2], af[mt][3],
                      aa + (mt * 16 * 20 + ks) * 4);
            #pragma unroll
            for (int np = 0; np < 2; np++)
                LDSM4(bf[2*np][0], bf[2*np][1], bf[2*np+1][0], bf[2*np+1][1],
                      bb + (np * 16 * 20 + ks) * 4);
            #pragma unroll
            for (int mt = 0; mt < 4; mt++)
                #pragma unroll
                for (int nt = 0; nt < 4; nt++)
                    mma_tf32(c[mt][nt], af[mt][0], af[mt][1], af[mt][2], af[mt][3],
                             bf[nt][0], bf[nt][1]);
        }

        if (t + 1 < T) {
            const int so = st ^ 1;
            *(uint4*)&As[so][lrow][lcol]     = make_uint4(f2tf32(pa0.x), f2tf32(pa0.y), f2tf32(pa0.z), f2tf32(pa0.w));
            *(uint4*)&As[so][lrow][lcol + 4] = make_uint4(f2tf32(pa1.x), f2tf32(pa1.y), f2tf32(pa1.z), f2tf32(pa1.w));
            *(uint4*)&Bs[so][lrow][lcol]     = make_uint4(f2tf32(pb0.x), f2tf32(pb0.y), f2tf32(pb0.z), f2tf32(pb0.w));
            *(uint4*)&Bs[so][lrow][lcol + 4] = make_uint4(f2tf32(pb1.x), f2tf32(pb1.y), f2tf32(pb1.z), f2tf32(pb1.w));
        }
    }

    #pragma unroll
    for (int mt = 0; mt < 4; mt++) {
        int row = blockIdx.y * 128 + wm * 64 + mt * 16 + g;
        #pragma unroll
        for (int nt = 0; nt < 4; nt++) {
            int col = blockIdx.x * 128 + wn * 32 + nt * 8 + 2 * tg;
            if (zz) {    // V: transposed tf32-rounded store
                Cv[(long)col * M + row]           = rtf(c[mt][nt][0]);
                Cv[(long)(col + 1) * M + row]     = rtf(c[mt][nt][1]);
                Cv[(long)col * M + row + 8]       = rtf(c[mt][nt][2]);
                Cv[(long)(col + 1) * M + row + 8] = rtf(c[mt][nt][3]);
            } else {     // K: normal f32 store (rope kernel follows)
                *(float2*)(Ck + (long)row * N + col)       = make_float2(c[mt][nt][0], c[mt][nt][1]);
                *(float2*)(Ck + (long)(row + 8) * N + col) = make_float2(c[mt][nt][2], c[mt][nt][3]);
            }
        }
    }
}

// ---------------- fused RoPE + RMSNorm + tf32 round (k path) ----------------
__global__ void rope_rmsnorm(float* __restrict__ t, const float* __restrict__ cosb,
                             const float* __restrict__ sinb, const float* __restrict__ w,
                             int nheads, int nrows, float scale)
{
    int row  = blockIdx.x * 8 + (threadIdx.x >> 5);
    if (row >= nrows) return;
    int lane = threadIdx.x & 31;
    int s    = row / nheads;

    float* p = t + row * HD;
    float2 xv = ((float2*)p)[lane];
    float c  = cosb[s * (HD / 2) + lane];
    float sn = sinb[s * (HD / 2) + lane];
    float orr = xv.x * c - xv.y * sn;
    float oi  = xv.x * sn + xv.y * c;

    float ss = orr * orr + oi * oi;
    #pragma unroll
    for (int o = 16; o; o >>= 1) ss += __shfl_xor_sync(0xffffffffu, ss, o);
    float inv = rsqrtf(ss * (1.f / HD) + 1e-6f) * scale;

    float2 wv = ((const float2*)w)[lane];
    ((float2*)p)[lane] = make_float2(rtf(orr * inv * wv.x), rtf(oi * inv * wv.y));
}

// ---------------- tensor-core flash attention: 128-row Q tile, 4 warps ------
#define KS_STAGE 4352
#define VS_OFF   8704
#define VS_STAGE 4352
#define ATTN_SMEM ((VS_OFF + 2 * VS_STAGE) * 4)

__global__ void __launch_bounds__(128) attn_tc(const float* __restrict__ q,
                                               const float* __restrict__ k,
                                               const float* __restrict__ vT,
                                               const float* __restrict__ gate,
                                               float* __restrict__ o)
{
    extern __shared__ uint32_t dsm[];
    const uint32_t sbase = smem_u32(dsm);

    const int b    = 15 - blockIdx.x;
    const int h    = blockIdx.y;
    const int kvh  = h >> 2;
    const int tid  = threadIdx.x;
    const int lane = tid & 31;
    const int w    = tid >> 5;
    const int g    = lane >> 2;
    const int tg   = lane & 3;
    const int qi0  = b * 128;
    const int KT   = 2 * b + 2;

    const int lr = tid >> 1;
    const int lc = (tid & 1) * 32;

    auto issueK = [&](int kb, int st) {
        const float* kp = k + (((long)(kb * 64 + lr)) * NKV + kvh) * HD + lc;
        uint32_t kd = sbase + (st * KS_STAGE + lr * 68 + lc) * 4;
        #pragma unroll
        for (int u = 0; u < 8; u++) CP16(kd + u * 16, kp + u * 4);
    };
    auto issueV = [&](int kb, int st) {
        const float* vp = vT + ((long)(kvh * HD + lr)) * SEQ + kb * 64 + lc;
        uint32_t vd = sbase + (VS_OFF + st * VS_STAGE + lr * 68 + lc) * 4;
        #pragma unroll
        for (int u = 0; u < 8; u++) CP16(vd + u * 16, vp + u * 4);
    };

    issueK(0, 0); CP_COMMIT();

    {
        const float* qp = q + (((long)(qi0 + tid)) * NH + h) * HD;
        uint32_t* dst = dsm + VS_OFF + tid * 68;
        #pragma unroll
        for (int u = 0; u < 16; u++)
            *(float4*)(dst + u * 4) = *(const float4*)(qp + u * 4);
    }
    __syncthreads();

    uint32_t qf[2][8][4];
    #pragma unroll
    for (int rg = 0; rg < 2; rg++) {
        const uint32_t qaddr = sbase + (VS_OFF + (w * 32 + rg * 16 + (lane & 15)) * 68
                                        + ((lane & 16) ? 4 : 0)) * 4;
        #pragma unroll
        for (int ks = 0; ks < 8; ks++)
            LDSM4(qf[rg][ks][0], qf[rg][ks][1], qf[rg][ks][2], qf[rg][ks][3],
                  qaddr + ks * 32);
    }
    __syncthreads();

    issueV(0, 0); CP_COMMIT();
    issueK(1, 1); issueV(1, 1); CP_COMMIT();

    const uint32_t kpat = sbase + (((lane & 7) + ((lane & 16) >> 1)) * 68 + ((lane & 8) ? 4 : 0)) * 4;
    const uint32_t vpat = sbase + (VS_OFF + ((lane & 7) + ((lane & 16) >> 1)) * 68 + ((lane & 8) ? 4 : 0)) * 4;

    float oacc[2][8][4];
    #pragma unroll
    for (int rg = 0; rg < 2; rg++)
        #pragma unroll
        for (int nt = 0; nt < 8; nt++)
            #pragma unroll
            for (int r = 0; r < 4; r++) oacc[rg][nt][r] = 0.f;
    float m[4] = {-1e30f, -1e30f, -1e30f, -1e30f};
    float l[4] = {0.f, 0.f, 0.f, 0.f};

    const int s0l  = (lane & ~3) + (tg >> 1);
    const int s2l  = s0l + 2;
    const bool odd = tg & 1;

    for (int kb = 0; kb < KT; kb++) {
        const int st = kb & 1;
        if (kb < KT - 1) { CP_WAIT(1); } else { CP_WAIT(0); }
        __syncthreads();

        float sc[2][8][4];
        #pragma unroll
        for (int rg = 0; rg < 2; rg++)
            #pragma unroll
            for (int nt = 0; nt < 8; nt++)
                #pragma unroll
                for (int r = 0; r < 4; r++) sc[rg][nt][r] = 0.f;

        const uint32_t kst = kpat + st * (KS_STAGE * 4);
        #pragma unroll
        for (int ks = 0; ks < 8; ks++) {
            #pragma unroll
            for (int np = 0; np < 4; np++) {
                uint32_t b00, b01, b10, b11;
                LDSM4(b00, b01, b10, b11, kst + (np * 16 * 68 + ks * 8) * 4);
                #pragma unroll
                for (int rg = 0; rg < 2; rg++) {
                    mma_tf32(sc[rg][2*np],   qf[rg][ks][0], qf[rg][ks][1],
                             qf[rg][ks][2], qf[rg][ks][3], b00, b01);
                    mma_tf32(sc[rg][2*np+1], qf[rg][ks][0], qf[rg][ks][1],
                             qf[rg][ks][2], qf[rg][ks][3], b10, b11);
                }
            }
        }

        if (kb >= 2 * b) {
            const int coff = (kb - 2 * b) * 64;
            #pragma unroll
            for (int rg = 0; rg < 2; rg++) {
                int r0 = w * 32 + rg * 16 + g, r1 = r0 + 8;
                #pragma unroll
                for (int nt = 0; nt < 8; nt++) {
                    int c0 = nt * 8 + 2 * tg + coff, c1 = c0 + 1;
                    if (c0 > r0) sc[rg][nt][0] = -1e30f;
                    if (c1 > r0) sc[rg][nt][1] = -1e30f;
                    if (c0 > r1) sc[rg][nt][2] = -1e30f;
                    if (c1 > r1) sc[rg][nt][3] = -1e30f;
                }
            }
        }

        #pragma unroll
        for (int rg = 0; rg < 2; rg++) {
            const int ia = rg * 2, ib = ia + 1;
            float mta = -1e30f, mtb = -1e30f;
            #pragma unroll
            for (int nt = 0; nt < 8; nt++) {
                mta = fmaxf(mta, fmaxf(sc[rg][nt][0], sc[rg][nt][1]));
                mtb = fmaxf(mtb, fmaxf(sc[rg][nt][2], sc[rg][nt][3]));
            }
            mta = fmaxf(mta, __shfl_xor_sync(0xffffffffu, mta, 1));
            mta = fmaxf(mta, __shfl_xor_sync(0xffffffffu, mta, 2));
            mtb = fmaxf(mtb, __shfl_xor_sync(0xffffffffu, mtb, 1));
            mtb = fmaxf(mtb, __shfl_xor_sync(0xffffffffu, mtb, 2));

            float mna = fmaxf(m[ia], mta), mnb = fmaxf(m[ib], mtb);
            float aa = ex2(m[ia] - mna),   ab = ex2(m[ib] - mnb);
            m[ia] = mna; m[ib] = mnb;

            float rsa = 0.f, rsb = 0.f;
            #pragma unroll
            for (int nt = 0; nt < 8; nt++) {
                float e0 = ex2(sc[rg][nt][0] - mna);
                float e1 = ex2(sc[rg][nt][1] - mna);
                float e2 = ex2(sc[rg][nt][2] - mnb);
                float e3 = ex2(sc[rg][nt][3] - mnb);
                rsa += e0 + e1;  rsb += e2 + e3;
                sc[rg][nt][0] = __uint_as_float(f2tf32(e0));
                sc[rg][nt][1] = __uint_as_float(f2tf32(e1));
                sc[rg][nt][2] = __uint_as_float(f2tf32(e2));
                sc[rg][nt][3] = __uint_as_float(f2tf32(e3));
            }
            rsa += __shfl_xor_sync(0xffffffffu, rsa, 1);
            rsa += __shfl_xor_sync(0xffffffffu, rsa, 2);
            rsb += __shfl_xor_sync(0xffffffffu, rsb, 1);
            rsb += __shfl_xor_sync(0xffffffffu, rsb, 2);
            l[ia] = l[ia] * aa + rsa;
            l[ib] = l[ib] * ab + rsb;

            #pragma unroll
            for (int nt = 0; nt < 8; nt++) {
                oacc[rg][nt][0] *= aa; oacc[rg][nt][1] *= aa;
                oacc[rg][nt][2] *= ab; oacc[rg][nt][3] *= ab;
            }
        }

        const uint32_t vst = vpat + st * (VS_STAGE * 4);
        #pragma unroll
        for (int ks = 0; ks < 8; ks++) {
            uint32_t pa[2][4];
            #pragma unroll
            for (int rg = 0; rg < 2; rg++) {
                float u0 = __shfl_sync(0xffffffffu, sc[rg][ks][0], s0l);
                float u1 = __shfl_sync(0xffffffffu, sc[rg][ks][1], s0l);
                float u2 = __shfl_sync(0xffffffffu, sc[rg][ks][2], s0l);
                float u3 = __shfl_sync(0xffffffffu, sc[rg][ks][3], s0l);
                float v0 = __shfl_sync(0xffffffffu, sc[rg][ks][0], s2l);
                float v1 = __shfl_sync(0xffffffffu, sc[rg][ks][1], s2l);
                float v2 = __shfl_sync(0xffffffffu, sc[rg][ks][2], s2l);
                float v3 = __shfl_sync(0xffffffffu, sc[rg][ks][3], s2l);
                pa[rg][0] = __float_as_uint(odd ? u1 : u0);
                pa[rg][1] = __float_as_uint(odd ? u3 : u2);
                pa[rg][2] = __float_as_uint(odd ? v1 : v0);
                pa[rg][3] = __float_as_uint(odd ? v3 : v2);
            }
            #pragma unroll
            for (int np = 0; np < 4; np++) {
                uint32_t b00, b01, b10, b11;
                LDSM4(b00, b01, b10, b11, vst + (np * 16 * 68 + ks * 8) * 4);
                #pragma unroll
                for (int rg = 0; rg < 2; rg++) {
                    mma_tf32(oacc[rg][2*np],   pa[rg][0], pa[rg][1], pa[rg][2], pa[rg][3], b00, b01);
                    mma_tf32(oacc[rg][2*np+1], pa[rg][0], pa[rg][1], pa[rg][2], pa[rg][3], b10, b11);
                }
            }
        }

        __syncthreads();
        if (kb + 2 < KT) { issueK(kb + 2, st); issueV(kb + 2, st); CP_COMMIT(); }
    }

    #pragma unroll
    for (int rg = 0; rg < 2; rg++) {
        float ila = 1.f / l[rg * 2], ilb = 1.f / l[rg * 2 + 1];
        int row0 = qi0 + w * 32 + rg * 16 + g;
        int row1 = row0 + 8;
        #pragma unroll
        for (int nt = 0; nt < 8; nt++) {
            int d = nt * 8 + 2 * tg;
            float2 ga = *(const float2*)(gate + (long)row0 * DIM + h * HD + d);
            float2 gb = *(const float2*)(gate + (long)row1 * DIM + h * HD + d);
            float2 o0, o1;
            o0.x = rtf(oacc[rg][nt][0] * ila * (1.f / (1.f + __expf(-ga.x))));
            o0.y = rtf(oacc[rg][nt][1] * ila * (1.f / (1.f + __expf(-ga.y))));
            o1.x = rtf(oacc[rg][nt][2] * ilb * (1.f / (1.f + __expf(-gb.x))));
            o1.y = rtf(oacc[rg][nt][3] * ilb * (1.f / (1.f + __expf(-gb.y))));
            *(float2*)(o + (long)row0 * DIM + h * HD + d) = o0;
            *(float2*)(o + (long)row1 * DIM + h * HD + d) = o1;
        }
    }
}

// ---------------- launcher: single stream (multi-stream regressed) ----------
extern "C" void kernel_launch(void* const* d_in, const int* in_sizes, int n_in,
                              void* d_out, int out_size)
{
    const float* x    = (const float*)d_in[0];
    const float* cosb = (const float*)d_in[1];
    const float* sinb = (const float*)d_in[2];
    const float* wq   = (const float*)d_in[3];
    const float* wk   = (const float*)d_in[4];
    const float* wv   = (const float*)d_in[5];
    const float* wo   = (const float*)d_in[6];
    const float* wg   = (const float*)d_in[7];
    const float* qn   = (const float*)d_in[8];
    const float* kn   = (const float*)d_in[9];
    float* out = (float*)d_out;

    float *qb, *kb, *vT, *gb, *ab;
    cudaGetSymbolAddress((void**)&qb, g_q);
    cudaGetSymbolAddress((void**)&kb, g_k);
    cudaGetSymbolAddress((void**)&vT, g_vT);
    cudaGetSymbolAddress((void**)&gb, g_gate);
    cudaGetSymbolAddress((void**)&ab, g_att);

    cudaFuncSetAttribute(attn_tc, cudaFuncAttributeMaxDynamicSharedMemorySize, ATTN_SMEM);

    const float QSCALE = 0.125f * 1.44269504088896f;

    // merged K+V projections (128 CTAs -> fills the chip)
    gemm_kv<<<dim3((NKV * HD) / 128, SEQ / 128, 2), 256>>>(x, wk, wv, kb, vT, SEQ, NKV * HD, DIM);

    // Q projection with fused RoPE+RMSNorm+scale (tf32-rounded output)
    gemm_big<1><<<dim3(DIM / 128, SEQ / 128), 128>>>(x, wq, qb, SEQ, DIM, DIM,
                                                     cosb, sinb, qn, QSCALE);

    // K RoPE (small)
    rope_rmsnorm<<<(SEQ * NKV) / 8, 256>>>(kb, cosb, sinb, kn, NKV, SEQ * NKV, 1.0f);

    // gate projection
    gemm_big<0><<<dim3(DIM / 128, SEQ / 128), 128>>>(x, wg, gb, SEQ, DIM, DIM,
                                                     nullptr, nullptr, nullptr, 0.f);

    // attention + fused sigmoid gate
    attn_tc<<<dim3(SEQ / 128, NH), 128, ATTN_SMEM>>>(qb, kb, vT, gb, ab);

    // output projection
    gemm_big<0><<<dim3(DIM / 128, SEQ / 128), 128>>>(ab, wo, out, SEQ, DIM, DIM,
                                                     nullptr, nullptr, nullptr, 0.f);
}